// round 11
// baseline (speedup 1.0000x reference)
#include <cuda_runtime.h>
#include <cuda_fp16.h>
#include <cstdint>

#define TOKENS 64
#define IN_F   8192
#define OUT_F  8192
#define NGROUPS (IN_F / 8)     // 1024
#define KSPLIT 4
#define NBLK   64              // outputs per block
#define HALF_F 4096

// K partition: tensor path k [0, 6656) = 416 k16 tiles; SIMT path groups [832, 1024)
#define KT_TENSOR 416
#define KT_PER    (KT_TENSOR / KSPLIT)   // 104
#define G_SIMT0   832
#define G_PER     ((NGROUPS - G_SIMT0) / KSPLIT)   // 48

// A fragments: [kt][mt][lane] -> uint4 (4 regs of m16k16 fp16 frag)
__device__ uint4 g_xa[512 * 4 * 32];                 // 1 MB
// xh fp32 rows [token][k] for SIMT path
__device__ float g_xf[TOKENS * IN_F];                // 2 MB
// partial outputs per K-split: [split][token][out]
__device__ float g_part[KSPLIT * TOKENS * OUT_F];    // 8 MB

#define INV_SQRT_8192 0.011048543456039806f

__device__ __forceinline__ int SW(int i) {
    return (i & ~31) | ((i ^ (i >> 5)) & 31);
}

#define FWHT_REG(a, N)                                            \
    _Pragma("unroll")                                             \
    for (int h = 1; h < (N); h <<= 1) {                           \
        _Pragma("unroll")                                         \
        for (int i = 0; i < (N); i++) {                           \
            if (!(i & h)) {                                       \
                float u = a[i], v = a[i ^ h];                     \
                a[i] = u + v; a[i ^ h] = u - v;                   \
            }                                                     \
        }                                                         \
    }

#define FWHT4096_BODY(s, tid, a, c)                               \
    FWHT_REG(a, 16)                                               \
    _Pragma("unroll")                                             \
    for (int j = 0; j < 16; j++)                                  \
        s[SW(tid + 256 * j)] = a[j];                              \
    __syncthreads();                                              \
    {                                                             \
        const int lo = tid & 15, hi = tid >> 4;                   \
        float bb[16];                                             \
        _Pragma("unroll")                                         \
        for (int j = 0; j < 16; j++)                              \
            bb[j] = s[SW(hi * 256 + j * 16 + lo)];                \
        FWHT_REG(bb, 16)                                          \
        __syncthreads();                                          \
        _Pragma("unroll")                                         \
        for (int j = 0; j < 16; j++)                              \
            s[SW(hi * 256 + j * 16 + lo)] = bb[j];                \
    }                                                             \
    __syncthreads();                                              \
    _Pragma("unroll")                                             \
    for (int i = 0; i < 16; i++)                                  \
        c[i] = s[SW(tid * 16 + i)];                               \
    FWHT_REG(c, 16)

// ---------------------------------------------------------------------------
// Kernel A: FWHT(x*SU)*scale -> fp16 A-fragments + fp32 rows. 2 blocks/token.
// ---------------------------------------------------------------------------
__global__ __launch_bounds__(256) void fwht_in_kernel(
    const float* __restrict__ x,
    const float* __restrict__ SU,
    const float* __restrict__ Wscale)
{
    __shared__ float s[HALF_F];
    const int t   = blockIdx.x >> 1;
    const int hb  = blockIdx.x & 1;
    const int tid = threadIdx.x;
    const float* xr = x + (size_t)t * IN_F;

    float a[16];
#pragma unroll
    for (int j = 0; j < 16; j++) {
        const int i = tid + 256 * j;
        const float v0 = xr[i] * SU[i];
        const float v1 = xr[i + HALF_F] * SU[i + HALF_F];
        a[j] = hb ? (v0 - v1) : (v0 + v1);
    }

    float c[16];
    FWHT4096_BODY(s, tid, a, c)

    const float scale = INV_SQRT_8192 * Wscale[0];
#pragma unroll
    for (int i = 0; i < 16; i++) c[i] *= scale;

    // fp32 rows for SIMT path (only k >= 6656 is read, write all: simpler)
    {
        float* dst = g_xf + (size_t)t * IN_F + hb * HALF_F + tid * 16;
#pragma unroll
        for (int v = 0; v < 4; v++)
            *(float4*)(dst + 4 * v) =
                make_float4(c[4*v], c[4*v+1], c[4*v+2], c[4*v+3]);
    }

    // fp16 A-fragment layout
    const int mt   = t >> 4;
    const int mrow = t & 15;
    const int kt   = hb * 256 + tid;
    uint32_t* xa = (uint32_t*)g_xa;
#pragma unroll
    for (int p = 0; p < 8; p++) {
        const int r    = p >> 2;
        const int lane = ((mrow & 7) << 2) | (p & 3);
        const int reg  = (r << 1) | (mrow >> 3);
        __half2 h = __floats2half2_rn(c[2 * p], c[2 * p + 1]);
        xa[(((kt * 4 + mt) * 32 + lane) << 2) + reg] = *(uint32_t*)&h;
    }

    cudaTriggerProgrammaticLaunchCompletion();
}

// ---------------------------------------------------------------------------
// Kernel B: dual-pipe GEMM. grid (128, 4), 256 threads, 2 blocks/SM.
//   warps 0-3: fp16 mma.sync, K [0, 6656)           (tensor pipe)
//   warps 4-7: fp32 FFMA dots, K [6656, 8192)        (fma pipe)
// SIMT results land in smem and are folded into the tensor store.
// ---------------------------------------------------------------------------
__device__ __forceinline__ void mma16816(float c[4], const uint4& a,
                                         uint32_t b0, uint32_t b1)
{
    asm volatile(
        "mma.sync.aligned.m16n8k16.row.col.f32.f16.f16.f32 "
        "{%0,%1,%2,%3},{%4,%5,%6,%7},{%8,%9},{%0,%1,%2,%3};\n"
        : "+f"(c[0]), "+f"(c[1]), "+f"(c[2]), "+f"(c[3])
        : "r"(a.x), "r"(a.y), "r"(a.z), "r"(a.w), "r"(b0), "r"(b1));
}

__global__ __launch_bounds__(256, 2) void gemm_kernel(
    const int*   __restrict__ Qidxs,
    const float* __restrict__ grid)
{
    __shared__ uint32_t cb[256 * 4];       // fp16 codebook (half2 pairs), 4 KB
    __shared__ float4   cbf[256 * 2];      // fp32 codebook (float4 pairs), 8 KB
    __shared__ float    red[NBLK * TOKENS];// SIMT partial, [o_local][t], 16 KB

    const int tid = threadIdx.x;
    // prologue (independent of fwht_in)
    {
        const float4* g4 = (const float4*)grid;
        float4 lo = g4[tid * 2], hi = g4[tid * 2 + 1];
        cbf[tid * 2]     = lo;
        cbf[tid * 2 + 1] = hi;
        __half2 h0 = __floats2half2_rn(lo.x, lo.y);
        __half2 h1 = __floats2half2_rn(lo.z, lo.w);
        __half2 h2 = __floats2half2_rn(hi.x, hi.y);
        __half2 h3 = __floats2half2_rn(hi.z, hi.w);
        cb[tid * 4 + 0] = *(uint32_t*)&h0;
        cb[tid * 4 + 1] = *(uint32_t*)&h1;
        cb[tid * 4 + 2] = *(uint32_t*)&h2;
        cb[tid * 4 + 3] = *(uint32_t*)&h3;
    }

    const int lane  = tid & 31;
    const int wid   = tid >> 5;
    const int oB    = blockIdx.x * NBLK;
    const int split = blockIdx.y;

    __syncthreads();                       // cb/cbf visible

    if (wid < 4) {
        // =================== tensor path ===================
        const int l4 = lane & 3;
        const int lq = lane >> 2;
        const int oW = oB + wid * 16;
        const int ktBase = split * KT_PER;
        const int ktEnd  = ktBase + KT_PER;

        const int2* qp0 = (const int2*)(Qidxs + (size_t)(oW + lq) * NGROUPS);
        const int2* qp1 = (const int2*)(Qidxs + (size_t)(oW + 8 + lq) * NGROUPS);

        int2 qB[2][2];
        qB[0][0] = qp0[ktBase];     qB[0][1] = qp1[ktBase];
        qB[1][0] = qp0[ktBase + 1]; qB[1][1] = qp1[ktBase + 1];

        float acc[2][4][4];
#pragma unroll
        for (int n = 0; n < 2; n++)
#pragma unroll
            for (int m = 0; m < 4; m++)
#pragma unroll
                for (int r = 0; r < 4; r++) acc[n][m][r] = 0.0f;

        cudaGridDependencySynchronize();   // wait for g_xa

        uint4 aB[2][4];
#pragma unroll
        for (int m = 0; m < 4; m++) {
            aB[0][m] = g_xa[((ktBase    ) * 4 + m) * 32 + lane];
            aB[1][m] = g_xa[((ktBase + 1) * 4 + m) * 32 + lane];
        }

        for (int kt = ktBase; kt < ktEnd; kt += 2) {
            {
                const uint32_t b00 = cb[(qB[0][0].x << 2) | l4];
                const uint32_t b01 = cb[(qB[0][0].y << 2) | l4];
                const uint32_t b10 = cb[(qB[0][1].x << 2) | l4];
                const uint32_t b11 = cb[(qB[0][1].y << 2) | l4];
#pragma unroll
                for (int m = 0; m < 4; m++) {
                    mma16816(acc[0][m], aB[0][m], b00, b01);
                    mma16816(acc[1][m], aB[0][m], b10, b11);
                }
                const int ktn = (kt + 2 < ktEnd) ? kt + 2 : ktEnd - 1;
#pragma unroll
                for (int m = 0; m < 4; m++)
                    aB[0][m] = g_xa[(ktn * 4 + m) * 32 + lane];
                qB[0][0] = qp0[ktn];
                qB[0][1] = qp1[ktn];
            }
            {
                const uint32_t b00 = cb[(qB[1][0].x << 2) | l4];
                const uint32_t b01 = cb[(qB[1][0].y << 2) | l4];
                const uint32_t b10 = cb[(qB[1][1].x << 2) | l4];
                const uint32_t b11 = cb[(qB[1][1].y << 2) | l4];
#pragma unroll
                for (int m = 0; m < 4; m++) {
                    mma16816(acc[0][m], aB[1][m], b00, b01);
                    mma16816(acc[1][m], aB[1][m], b10, b11);
                }
                const int ktn = (kt + 3 < ktEnd) ? kt + 3 : ktEnd - 1;
#pragma unroll
                for (int m = 0; m < 4; m++)
                    aB[1][m] = g_xa[(ktn * 4 + m) * 32 + lane];
                qB[1][0] = qp0[ktn];
                qB[1][1] = qp1[ktn];
            }
        }

        __syncthreads();                    // wait SIMT partials in red

        float* base = g_part + (size_t)split * TOKENS * OUT_F;
#pragma unroll
        for (int n = 0; n < 2; n++) {
            const int o  = oW + n * 8 + 2 * l4;
            const int ol = o - oB;
#pragma unroll
            for (int m = 0; m < 4; m++) {
                const int t0 = m * 16 + lq;
                float2 v0, v1;
                v0.x = acc[n][m][0] + red[ol * TOKENS + t0];
                v0.y = acc[n][m][1] + red[(ol + 1) * TOKENS + t0];
                v1.x = acc[n][m][2] + red[ol * TOKENS + t0 + 8];
                v1.y = acc[n][m][3] + red[(ol + 1) * TOKENS + t0 + 8];
                *(float2*)&base[(size_t)t0 * OUT_F + o]       = v0;
                *(float2*)&base[(size_t)(t0 + 8) * OUT_F + o] = v1;
            }
        }
    } else {
        // =================== SIMT fp32 path ===================
        const int wq = wid - 4;
        const int oS = oB + wq * 16;           // 16 outputs: 2 octets of 8
        const int t0 = 2 * lane;               // 2 tokens per lane
        const int gBase = G_SIMT0 + split * G_PER;

        float acc[2][8][2];                    // [octet][i][token]
#pragma unroll
        for (int oc = 0; oc < 2; oc++)
#pragma unroll
            for (int i = 0; i < 8; i++)
                acc[oc][i][0] = acc[oc][i][1] = 0.0f;

        cudaGridDependencySynchronize();       // wait for g_xf

        const float4* x0 = (const float4*)(g_xf + (size_t)t0 * IN_F);
        const float4* x1 = (const float4*)(g_xf + (size_t)(t0 + 1) * IN_F);

        for (int g = gBase; g < gBase + G_PER; g++) {
            const float4 a0 = x0[g * 2], a1 = x0[g * 2 + 1];
            const float4 b0 = x1[g * 2], b1 = x1[g * 2 + 1];
#pragma unroll
            for (int oc = 0; oc < 2; oc++) {
                const int obase = oS + oc * 8;
#pragma unroll
                for (int i = 0; i < 8; i++) {
                    const int q = Qidxs[(size_t)(obase + i) * NGROUPS + g];
                    const float4 w0 = cbf[q * 2];
                    const float4 w1 = cbf[q * 2 + 1];
                    float s0 = acc[oc][i][0];
                    s0 = fmaf(a0.x, w0.x, s0); s0 = fmaf(a0.y, w0.y, s0);
                    s0 = fmaf(a0.z, w0.z, s0); s0 = fmaf(a0.w, w0.w, s0);
                    s0 = fmaf(a1.x, w1.x, s0); s0 = fmaf(a1.y, w1.y, s0);
                    s0 = fmaf(a1.z, w1.z, s0); s0 = fmaf(a1.w, w1.w, s0);
                    acc[oc][i][0] = s0;
                    float s1 = acc[oc][i][1];
                    s1 = fmaf(b0.x, w0.x, s1); s1 = fmaf(b0.y, w0.y, s1);
                    s1 = fmaf(b0.z, w0.z, s1); s1 = fmaf(b0.w, w0.w, s1);
                    s1 = fmaf(b1.x, w1.x, s1); s1 = fmaf(b1.y, w1.y, s1);
                    s1 = fmaf(b1.z, w1.z, s1); s1 = fmaf(b1.w, w1.w, s1);
                    acc[oc][i][1] = s1;
                }
            }
        }

        // publish to reduce buffer: red[o_local][t]
#pragma unroll
        for (int oc = 0; oc < 2; oc++)
#pragma unroll
            for (int i = 0; i < 8; i++) {
                const int ol = wq * 16 + oc * 8 + i;
                *(float2*)&red[ol * TOKENS + t0] =
                    make_float2(acc[oc][i][0], acc[oc][i][1]);
            }

        __syncthreads();                       // release tensor warps
    }

    cudaTriggerProgrammaticLaunchCompletion();
}

// ---------------------------------------------------------------------------
// Kernel C: sum KSPLIT partials (folded stride-4096 butterfly), FWHT_4096,
// * SV/sqrt + bias. 2 blocks per token. PDL consumer.
// ---------------------------------------------------------------------------
__global__ __launch_bounds__(256) void fwht_out_kernel(
    const float* __restrict__ SV,
    const float* __restrict__ bias,
    float* __restrict__ out)
{
    __shared__ float s[HALF_F];
    const int t   = blockIdx.x >> 1;
    const int hb  = blockIdx.x & 1;
    const int tid = threadIdx.x;

    cudaGridDependencySynchronize();

    float a[16];
#pragma unroll
    for (int j = 0; j < 16; j++) {
        const int i = tid + 256 * j;
        float v0 = 0.0f, v1 = 0.0f;
#pragma unroll
        for (int p = 0; p < KSPLIT; p++) {
            const float* row = g_part + (size_t)(p * TOKENS + t) * OUT_F;
            v0 += row[i];
            v1 += row[i + HALF_F];
        }
        a[j] = hb ? (v0 - v1) : (v0 + v1);
    }

    float c[16];
    FWHT4096_BODY(s, tid, a, c)

    float* orow = out + (size_t)t * OUT_F + hb * HALF_F;
#pragma unroll
    for (int i = 0; i < 16; i++) {
        const int idx = tid * 16 + i;
        const int gidx = hb * HALF_F + idx;
        orow[idx] = c[i] * INV_SQRT_8192 * SV[gidx] + bias[gidx];
    }
}

// ---------------------------------------------------------------------------
// Inputs (metadata order): x, SU, SV, grid, Wscale, bias, Qidxs
// ---------------------------------------------------------------------------
extern "C" void kernel_launch(void* const* d_in, const int* in_sizes, int n_in,
                              void* d_out, int out_size)
{
    const float* x      = (const float*)d_in[0];
    const float* SU     = (const float*)d_in[1];
    const float* SV     = (const float*)d_in[2];
    const float* grid   = (const float*)d_in[3];
    const float* Wscale = (const float*)d_in[4];
    const float* bias   = (const float*)d_in[5];
    const int*   Qidxs  = (const int*)  d_in[6];
    float*       out    = (float*)d_out;

    fwht_in_kernel<<<2 * TOKENS, 256>>>(x, SU, Wscale);

    {
        cudaLaunchConfig_t cfg = {};
        cfg.gridDim  = dim3(OUT_F / NBLK, KSPLIT, 1);
        cfg.blockDim = dim3(256, 1, 1);
        cudaLaunchAttribute attr[1];
        attr[0].id = cudaLaunchAttributeProgrammaticStreamSerialization;
        attr[0].val.programmaticStreamSerializationAllowed = 1;
        cfg.attrs = attr;
        cfg.numAttrs = 1;
        cudaLaunchKernelEx(&cfg, gemm_kernel, Qidxs, grid);
    }

    {
        cudaLaunchConfig_t cfg = {};
        cfg.gridDim  = dim3(2 * TOKENS, 1, 1);
        cfg.blockDim = dim3(256, 1, 1);
        cudaLaunchAttribute attr[1];
        attr[0].id = cudaLaunchAttributeProgrammaticStreamSerialization;
        attr[0].val.programmaticStreamSerializationAllowed = 1;
        cfg.attrs = attr;
        cfg.numAttrs = 1;
        cudaLaunchKernelEx(&cfg, fwht_out_kernel, SV, bias, out);
    }
}

// round 12
// speedup vs baseline: 2.2472x; 2.2472x over previous
#include <cuda_runtime.h>
#include <cuda_fp16.h>
#include <cstdint>

#define TOKENS 64
#define IN_F   8192
#define OUT_F  8192
#define NGROUPS (IN_F / 8)     // 1024
#define KT_TILES (IN_F / 16)   // 512 k16 tiles
#define KSPLIT 4
#define NBLK   64              // N per block (4 warps x N16)
#define HALF_F 4096

// A fragments: [kt][mt][lane] -> uint4 (4 regs of m16k16 fp16 frag)
__device__ uint4 g_xa[KT_TILES * 4 * 32];            // 1 MB
// accumulated output [token][out] (REDG target, zeroed by fwht_in)
__device__ float g_acc[TOKENS * OUT_F];              // 2 MB

#define INV_SQRT_8192 0.011048543456039806f

__device__ __forceinline__ int SW(int i) {
    return (i & ~31) | ((i ^ (i >> 5)) & 31);
}

#define FWHT_REG(a, N)                                            \
    _Pragma("unroll")                                             \
    for (int h = 1; h < (N); h <<= 1) {                           \
        _Pragma("unroll")                                         \
        for (int i = 0; i < (N); i++) {                           \
            if (!(i & h)) {                                       \
                float u = a[i], v = a[i ^ h];                     \
                a[i] = u + v; a[i ^ h] = u - v;                   \
            }                                                     \
        }                                                         \
    }

#define FWHT4096_BODY(s, tid, a, c)                               \
    FWHT_REG(a, 16)                                               \
    _Pragma("unroll")                                             \
    for (int j = 0; j < 16; j++)                                  \
        s[SW(tid + 256 * j)] = a[j];                              \
    __syncthreads();                                              \
    {                                                             \
        const int lo = tid & 15, hi = tid >> 4;                   \
        float bb[16];                                             \
        _Pragma("unroll")                                         \
        for (int j = 0; j < 16; j++)                              \
            bb[j] = s[SW(hi * 256 + j * 16 + lo)];                \
        FWHT_REG(bb, 16)                                          \
        __syncthreads();                                          \
        _Pragma("unroll")                                         \
        for (int j = 0; j < 16; j++)                              \
            s[SW(hi * 256 + j * 16 + lo)] = bb[j];                \
    }                                                             \
    __syncthreads();                                              \
    _Pragma("unroll")                                             \
    for (int i = 0; i < 16; i++)                                  \
        c[i] = s[SW(tid * 16 + i)];                               \
    FWHT_REG(c, 16)

// ---------------------------------------------------------------------------
// Kernel A: zero g_acc slice + FWHT(x*SU)*scale -> fp16 A-fragments.
// 2 blocks per token. PDL producer.
// ---------------------------------------------------------------------------
__global__ __launch_bounds__(256) void fwht_in_kernel(
    const float* __restrict__ x,
    const float* __restrict__ SU,
    const float* __restrict__ Wscale)
{
    __shared__ float s[HALF_F];               // 16 KB
    const int t   = blockIdx.x >> 1;
    const int hb  = blockIdx.x & 1;
    const int tid = threadIdx.x;
    const float* xr = x + (size_t)t * IN_F;

    // zero this block's 16 KB slice of g_acc (4096 floats)
    {
        float4* z = (float4*)(g_acc + (size_t)blockIdx.x * 4096) + tid;
#pragma unroll
        for (int v = 0; v < 4; v++)
            z[v * 256] = make_float4(0.f, 0.f, 0.f, 0.f);
    }

    float a[16];
#pragma unroll
    for (int j = 0; j < 16; j++) {
        const int i = tid + 256 * j;
        const float v0 = xr[i] * SU[i];
        const float v1 = xr[i + HALF_F] * SU[i + HALF_F];
        a[j] = hb ? (v0 - v1) : (v0 + v1);
    }

    float c[16];
    FWHT4096_BODY(s, tid, a, c)

    const float scale = INV_SQRT_8192 * Wscale[0];
    const int mt   = t >> 4;
    const int mrow = t & 15;
    const int kt   = hb * 256 + tid;          // this thread's k16 tile
    uint32_t* xa = (uint32_t*)g_xa;
#pragma unroll
    for (int p = 0; p < 8; p++) {
        const int r    = p >> 2;
        const int lane = ((mrow & 7) << 2) | (p & 3);
        const int reg  = (r << 1) | (mrow >> 3);
        __half2 h = __floats2half2_rn(c[2 * p] * scale, c[2 * p + 1] * scale);
        xa[(((kt * 4 + mt) * 32 + lane) << 2) + reg] = *(uint32_t*)&h;
    }

    cudaTriggerProgrammaticLaunchCompletion();
}

// ---------------------------------------------------------------------------
// Kernel B: fused codebook-decode + fp16 mma.sync GEMM.
// Epilogue: REDG (atomicAdd, no return) into g_acc — single accumulated
// buffer, no partials round-trip. PDL both sides.
// ---------------------------------------------------------------------------
__device__ __forceinline__ void mma16816(float c[4], const uint4& a,
                                         uint32_t b0, uint32_t b1)
{
    asm volatile(
        "mma.sync.aligned.m16n8k16.row.col.f32.f16.f16.f32 "
        "{%0,%1,%2,%3},{%4,%5,%6,%7},{%8,%9},{%0,%1,%2,%3};\n"
        : "+f"(c[0]), "+f"(c[1]), "+f"(c[2]), "+f"(c[3])
        : "r"(a.x), "r"(a.y), "r"(a.z), "r"(a.w), "r"(b0), "r"(b1));
}

__global__ __launch_bounds__(128) void gemm_kernel(
    const int*   __restrict__ Qidxs,
    const float* __restrict__ grid)
{
    __shared__ uint32_t cb[256 * 4];     // codebook as half2: [code][pair]
    const int tid = threadIdx.x;
    // prologue (independent of fwht_in): codebook convert + store
    for (int i = tid; i < 1024; i += 128) {
        int c = i >> 2, j = i & 3;
        __half2 h = __floats2half2_rn(grid[c * 8 + 2 * j], grid[c * 8 + 2 * j + 1]);
        cb[i] = *(uint32_t*)&h;
    }

    const int lane = tid & 31;
    const int w    = tid >> 5;
    const int l4   = lane & 3;
    const int lq   = lane >> 2;
    const int oW   = blockIdx.x * NBLK + w * 16;
    const int split = blockIdx.y;

    const int ktBase = split * (KT_TILES / KSPLIT);   // 128 tiles per split
    const int ktEnd  = ktBase + (KT_TILES / KSPLIT);

    const int2* qp0 = (const int2*)(Qidxs + (size_t)(oW + lq) * NGROUPS);
    const int2* qp1 = (const int2*)(Qidxs + (size_t)(oW + 8 + lq) * NGROUPS);

    // Qidxs prefetch (input tensor — independent of fwht_in)
    int2 qB[2][2];
    qB[0][0] = qp0[ktBase];     qB[0][1] = qp1[ktBase];
    qB[1][0] = qp0[ktBase + 1]; qB[1][1] = qp1[ktBase + 1];

    float acc[2][4][4];
#pragma unroll
    for (int n = 0; n < 2; n++)
#pragma unroll
        for (int m = 0; m < 4; m++)
#pragma unroll
            for (int r = 0; r < 4; r++) acc[n][m][r] = 0.0f;

    __syncthreads();                       // cb visible

    // wait for fwht_in (g_acc zeroed + g_xa ready)
    cudaGridDependencySynchronize();

    uint4 aB[2][4];
#pragma unroll
    for (int m = 0; m < 4; m++) {
        aB[0][m] = g_xa[((ktBase    ) * 4 + m) * 32 + lane];
        aB[1][m] = g_xa[((ktBase + 1) * 4 + m) * 32 + lane];
    }

    for (int kt = ktBase; kt < ktEnd; kt += 2) {
        {
            const uint32_t b00 = cb[(qB[0][0].x << 2) | l4];
            const uint32_t b01 = cb[(qB[0][0].y << 2) | l4];
            const uint32_t b10 = cb[(qB[0][1].x << 2) | l4];
            const uint32_t b11 = cb[(qB[0][1].y << 2) | l4];
#pragma unroll
            for (int m = 0; m < 4; m++) {
                mma16816(acc[0][m], aB[0][m], b00, b01);
                mma16816(acc[1][m], aB[0][m], b10, b11);
            }
            const int ktn = (kt + 2 < ktEnd) ? kt + 2 : ktEnd - 1;
#pragma unroll
            for (int m = 0; m < 4; m++)
                aB[0][m] = g_xa[(ktn * 4 + m) * 32 + lane];
            qB[0][0] = qp0[ktn];
            qB[0][1] = qp1[ktn];
        }
        {
            const uint32_t b00 = cb[(qB[1][0].x << 2) | l4];
            const uint32_t b01 = cb[(qB[1][0].y << 2) | l4];
            const uint32_t b10 = cb[(qB[1][1].x << 2) | l4];
            const uint32_t b11 = cb[(qB[1][1].y << 2) | l4];
#pragma unroll
            for (int m = 0; m < 4; m++) {
                mma16816(acc[0][m], aB[1][m], b00, b01);
                mma16816(acc[1][m], aB[1][m], b10, b11);
            }
            const int ktn = (kt + 3 < ktEnd) ? kt + 3 : ktEnd - 1;
#pragma unroll
            for (int m = 0; m < 4; m++)
                aB[1][m] = g_xa[(ktn * 4 + m) * 32 + lane];
            qB[1][0] = qp0[ktn];
            qB[1][1] = qp1[ktn];
        }
    }

    // epilogue: REDG accumulate (return value unused -> RED in SASS)
#pragma unroll
    for (int n = 0; n < 2; n++) {
        const int o = oW + n * 8 + 2 * l4;
#pragma unroll
        for (int m = 0; m < 4; m++) {
            const int t0 = m * 16 + lq;
            atomicAdd(&g_acc[(size_t)t0 * OUT_F + o],           acc[n][m][0]);
            atomicAdd(&g_acc[(size_t)t0 * OUT_F + o + 1],       acc[n][m][1]);
            atomicAdd(&g_acc[(size_t)(t0 + 8) * OUT_F + o],     acc[n][m][2]);
            atomicAdd(&g_acc[(size_t)(t0 + 8) * OUT_F + o + 1], acc[n][m][3]);
        }
    }

    cudaTriggerProgrammaticLaunchCompletion();
}

// ---------------------------------------------------------------------------
// Kernel C: read accumulated g_acc (folded stride-4096 butterfly),
// FWHT_4096, * SV/sqrt + bias. 2 blocks per token. PDL consumer.
// ---------------------------------------------------------------------------
__global__ __launch_bounds__(256) void fwht_out_kernel(
    const float* __restrict__ SV,
    const float* __restrict__ bias,
    float* __restrict__ out)
{
    __shared__ float s[HALF_F];
    const int t   = blockIdx.x >> 1;
    const int hb  = blockIdx.x & 1;
    const int tid = threadIdx.x;

    cudaGridDependencySynchronize();

    const float* row = g_acc + (size_t)t * OUT_F;
    float a[16];
#pragma unroll
    for (int j = 0; j < 16; j++) {
        const int i = tid + 256 * j;
        const float v0 = row[i];
        const float v1 = row[i + HALF_F];
        a[j] = hb ? (v0 - v1) : (v0 + v1);
    }

    float c[16];
    FWHT4096_BODY(s, tid, a, c)

    float* orow = out + (size_t)t * OUT_F + hb * HALF_F;
#pragma unroll
    for (int i = 0; i < 16; i++) {
        const int idx = tid * 16 + i;
        const int gidx = hb * HALF_F + idx;
        orow[idx] = c[i] * INV_SQRT_8192 * SV[gidx] + bias[gidx];
    }
}

// ---------------------------------------------------------------------------
// Inputs (metadata order): x, SU, SV, grid, Wscale, bias, Qidxs
// ---------------------------------------------------------------------------
extern "C" void kernel_launch(void* const* d_in, const int* in_sizes, int n_in,
                              void* d_out, int out_size)
{
    const float* x      = (const float*)d_in[0];
    const float* SU     = (const float*)d_in[1];
    const float* SV     = (const float*)d_in[2];
    const float* grid   = (const float*)d_in[3];
    const float* Wscale = (const float*)d_in[4];
    const float* bias   = (const float*)d_in[5];
    const int*   Qidxs  = (const int*)  d_in[6];
    float*       out    = (float*)d_out;

    fwht_in_kernel<<<2 * TOKENS, 256>>>(x, SU, Wscale);

    {
        cudaLaunchConfig_t cfg = {};
        cfg.gridDim  = dim3(OUT_F / NBLK, KSPLIT, 1);
        cfg.blockDim = dim3(128, 1, 1);
        cudaLaunchAttribute attr[1];
        attr[0].id = cudaLaunchAttributeProgrammaticStreamSerialization;
        attr[0].val.programmaticStreamSerializationAllowed = 1;
        cfg.attrs = attr;
        cfg.numAttrs = 1;
        cudaLaunchKernelEx(&cfg, gemm_kernel, Qidxs, grid);
    }

    {
        cudaLaunchConfig_t cfg = {};
        cfg.gridDim  = dim3(2 * TOKENS, 1, 1);
        cfg.blockDim = dim3(256, 1, 1);
        cudaLaunchAttribute attr[1];
        attr[0].id = cudaLaunchAttributeProgrammaticStreamSerialization;
        attr[0].val.programmaticStreamSerializationAllowed = 1;
        cfg.attrs = attr;
        cfg.numAttrs = 1;
        cudaLaunchKernelEx(&cfg, fwht_out_kernel, SV, bias, out);
    }
}